// round 3
// baseline (speedup 1.0000x reference)
#include <cuda_runtime.h>
#include <math.h>

#define B_  64
#define N_  512
#define C_  768
#define H_  12
#define HD  64

// Scratch (allocation-free contract -> __device__ globals)
// g_qkv layout: [which][b][h][n][d]
__device__ float g_qkv[3ULL * B_ * H_ * N_ * HD];   // ~302 MB
// g_att layout: [b][n][h*64+d] == [M, C]
__device__ float g_att[(size_t)B_ * N_ * C_];       // ~100 MB

// ---------------------------------------------------------------------------
// GEMM: out = A[M,K] @ W[N,K]^T   (both row-major, K contiguous: "NT")
// BM=128, BN=64, BK=16, 256 threads, 8x4 micro-tile per thread.
// MODE 0: A = x, scatter into g_qkv (QKV projection)
// MODE 1: A = g_att, add bias, write out (output projection)
// ---------------------------------------------------------------------------
template<int MODE>
__global__ __launch_bounds__(256)
void gemm_nt(const float* __restrict__ A,
             const float* __restrict__ W,
             const float* __restrict__ bias,
             float* __restrict__ out, int K)
{
    const int BK = 16;
    __shared__ float As[BK][132];   // As[k][m], 128 rows + pad
    __shared__ float Ws[BK][68];    // Ws[k][n], 64 rows + pad

    const float* Ap = (MODE == 1) ? (const float*)g_att : A;

    int m0 = blockIdx.y * 128;
    int n0 = blockIdx.x * 64;
    int tid = threadIdx.x;
    int tx = tid & 15;          // n direction: 16 threads * 4 cols
    int tyy = tid >> 4;         // m direction: 16 threads * 8 rows

    float acc[8][4];
#pragma unroll
    for (int i = 0; i < 8; i++)
#pragma unroll
        for (int j = 0; j < 4; j++) acc[i][j] = 0.f;

    int arow = tid >> 2;        // 0..63
    int akq  = tid & 3;         // which float4 in the 16-wide k slab
    const float* aptr1 = Ap + (size_t)(m0 + arow) * K + akq * 4;
    const float* aptr2 = Ap + (size_t)(m0 + 64 + arow) * K + akq * 4;
    const float* wptr  = W  + (size_t)(n0 + arow) * K + akq * 4;

    for (int k0 = 0; k0 < K; k0 += BK) {
        float4 av1 = *(const float4*)(aptr1 + k0);
        float4 av2 = *(const float4*)(aptr2 + k0);
        float4 wv  = *(const float4*)(wptr + k0);
        int kb = akq * 4;
        As[kb + 0][arow] = av1.x;  As[kb + 1][arow] = av1.y;
        As[kb + 2][arow] = av1.z;  As[kb + 3][arow] = av1.w;
        As[kb + 0][arow + 64] = av2.x;  As[kb + 1][arow + 64] = av2.y;
        As[kb + 2][arow + 64] = av2.z;  As[kb + 3][arow + 64] = av2.w;
        Ws[kb + 0][arow] = wv.x;  Ws[kb + 1][arow] = wv.y;
        Ws[kb + 2][arow] = wv.z;  Ws[kb + 3][arow] = wv.w;
        __syncthreads();

#pragma unroll
        for (int kk = 0; kk < BK; kk++) {
            float4 a0 = *(const float4*)&As[kk][tyy * 8];
            float4 a1 = *(const float4*)&As[kk][tyy * 8 + 4];
            float4 b0 = *(const float4*)&Ws[kk][tx * 4];
            float a[8] = {a0.x, a0.y, a0.z, a0.w, a1.x, a1.y, a1.z, a1.w};
            float bb[4] = {b0.x, b0.y, b0.z, b0.w};
#pragma unroll
            for (int i = 0; i < 8; i++)
#pragma unroll
                for (int j = 0; j < 4; j++)
                    acc[i][j] = fmaf(a[i], bb[j], acc[i][j]);
        }
        __syncthreads();
    }

    if (MODE == 0) {
        // scatter to q/k/v: col n = which*768 + h*64 + d  (n-tile is 64-wide and
        // 64-aligned, so (which, h) constant within this block's column range)
        int n_base = n0 + tx * 4;
        int which = n_base / C_;
        int rem = n_base - which * C_;
        int h = rem >> 6;
        int d = rem & 63;
        float* basep = g_qkv + (size_t)which * (B_ * H_ * N_ * HD);
#pragma unroll
        for (int i = 0; i < 8; i++) {
            int m = m0 + tyy * 8 + i;
            int b = m >> 9;
            int nn = m & 511;
            float* dst = basep + (((size_t)(b * H_ + h) * N_ + nn) * HD) + d;
            *(float4*)dst = make_float4(acc[i][0], acc[i][1], acc[i][2], acc[i][3]);
        }
    } else {
        float4 bv = *(const float4*)(bias + n0 + tx * 4);
#pragma unroll
        for (int i = 0; i < 8; i++) {
            int m = m0 + tyy * 8 + i;
            float4 ov = make_float4(acc[i][0] + bv.x, acc[i][1] + bv.y,
                                    acc[i][2] + bv.z, acc[i][3] + bv.w);
            *(float4*)(out + (size_t)m * C_ + n0 + tx * 4) = ov;
        }
    }
}

// ---------------------------------------------------------------------------
// Flash-style attention: one CTA per (b,h, 64-query tile). 256 threads.
// Thread (ty,tx) = (tid>>4, tid&15): 4 rows x 4 cols micro-tile.
// Q,K stored d-major [d][row] stride 68; V,P stored k-major stride 68.
// Online softmax with per-row (m,l) kept redundantly by the 16 tx threads.
// ---------------------------------------------------------------------------
__global__ __launch_bounds__(256)
void attn_kernel(const float* __restrict__ bias_table)
{
    const int ST = 68;
    extern __shared__ float sm[];
    float* Qs  = sm;               // [64][68]  Qs[d][row]
    float* Ks  = Qs + 64 * ST;     // [64][68]  Ks[d][key]
    float* Vs  = Ks + 64 * ST;     // [64][68]  Vs[k][d]
    float* Ps  = Vs + 64 * ST;     // [64][68]  Ps[k][row]
    float* bsh = Ps + 64 * ST;     // [127]

    int bh = blockIdx.y;           // 0..767
    int b = bh / H_;
    int h = bh - b * H_;
    int i0 = blockIdx.x * 64;

    const float* qb = g_qkv + (size_t)bh * N_ * HD;
    const float* kb = qb + (size_t)B_ * H_ * N_ * HD;
    const float* vb = kb + (size_t)B_ * H_ * N_ * HD;

    int tid = threadIdx.x;
    int tx = tid & 15;
    int ty = tid >> 4;

    // load Q tile transposed, float4 global loads (HD contiguous)
    for (int idx = tid; idx < 1024; idx += 256) {
        int r = idx >> 4;            // 0..63
        int dq = (idx & 15) * 4;     // 0,4,...,60
        float4 v = *(const float4*)(qb + (size_t)(i0 + r) * HD + dq);
        Qs[(dq + 0) * ST + r] = v.x;
        Qs[(dq + 1) * ST + r] = v.y;
        Qs[(dq + 2) * ST + r] = v.z;
        Qs[(dq + 3) * ST + r] = v.w;
    }

    float m_[4], l_[4], o_[4][4];
#pragma unroll
    for (int i = 0; i < 4; i++) {
        m_[i] = -1e30f; l_[i] = 0.f;
#pragma unroll
        for (int j = 0; j < 4; j++) o_[i][j] = 0.f;
    }

    const float scale = 0.125f;   // hd^-0.5 = 1/8

    for (int kt = 0; kt < 8; kt++) {
        // load K (transposed) and V tiles, float4 global loads
        for (int idx = tid; idx < 1024; idx += 256) {
            int r = idx >> 4;
            int dq = (idx & 15) * 4;
            float4 kv4 = *(const float4*)(kb + (size_t)(kt * 64 + r) * HD + dq);
            float4 vv4 = *(const float4*)(vb + (size_t)(kt * 64 + r) * HD + dq);
            Ks[(dq + 0) * ST + r] = kv4.x;
            Ks[(dq + 1) * ST + r] = kv4.y;
            Ks[(dq + 2) * ST + r] = kv4.z;
            Ks[(dq + 3) * ST + r] = kv4.w;
            *(float4*)&Vs[r * ST + dq] = vv4;
        }
        // bias slab: rel = i - j + 511, local t = (i-i0)-(j-j0)+63 in [0,126]
        if (tid < 127) {
            int rel = i0 - kt * 64 + 448 + tid;
            bsh[tid] = bias_table[rel * H_ + h];
        }
        __syncthreads();

        // S = Q K^T
        float s[4][4];
#pragma unroll
        for (int i = 0; i < 4; i++)
#pragma unroll
            for (int j = 0; j < 4; j++) s[i][j] = 0.f;

#pragma unroll 8
        for (int d = 0; d < 64; d++) {
            float4 qv = *(const float4*)&Qs[d * ST + ty * 4];
            float4 kv = *(const float4*)&Ks[d * ST + tx * 4];
            float qa[4] = {qv.x, qv.y, qv.z, qv.w};
            float ka[4] = {kv.x, kv.y, kv.z, kv.w};
#pragma unroll
            for (int i = 0; i < 4; i++)
#pragma unroll
                for (int j = 0; j < 4; j++)
                    s[i][j] = fmaf(qa[i], ka[j], s[i][j]);
        }

        // scale + bias, tile row-max
        float mt[4];
#pragma unroll
        for (int i = 0; i < 4; i++) {
            mt[i] = -1e30f;
#pragma unroll
            for (int j = 0; j < 4; j++) {
                s[i][j] = s[i][j] * scale + bsh[(ty * 4 + i) - (tx * 4 + j) + 63];
                mt[i] = fmaxf(mt[i], s[i][j]);
            }
        }
#pragma unroll
        for (int off = 8; off > 0; off >>= 1)
#pragma unroll
            for (int i = 0; i < 4; i++)
                mt[i] = fmaxf(mt[i], __shfl_xor_sync(0xffffffffu, mt[i], off, 16));

        // online softmax update
        float alpha[4], rs[4];
#pragma unroll
        for (int i = 0; i < 4; i++) {
            float mn = fmaxf(m_[i], mt[i]);
            alpha[i] = __expf(m_[i] - mn);
            m_[i] = mn;
            float r = 0.f;
#pragma unroll
            for (int j = 0; j < 4; j++) {
                s[i][j] = __expf(s[i][j] - mn);
                r += s[i][j];
            }
            rs[i] = r;
        }
#pragma unroll
        for (int off = 8; off > 0; off >>= 1)
#pragma unroll
            for (int i = 0; i < 4; i++)
                rs[i] += __shfl_xor_sync(0xffffffffu, rs[i], off, 16);
#pragma unroll
        for (int i = 0; i < 4; i++) {
            l_[i] = l_[i] * alpha[i] + rs[i];
#pragma unroll
            for (int j = 0; j < 4; j++) o_[i][j] *= alpha[i];
        }

        // write P transposed: Ps[key][row]
#pragma unroll
        for (int j = 0; j < 4; j++)
#pragma unroll
            for (int i = 0; i < 4; i++)
                Ps[(tx * 4 + j) * ST + ty * 4 + i] = s[i][j];
        __syncthreads();

        // O += P @ V
#pragma unroll 8
        for (int kk = 0; kk < 64; kk++) {
            float4 pv = *(const float4*)&Ps[kk * ST + ty * 4];
            float4 vv = *(const float4*)&Vs[kk * ST + tx * 4];
            float pa[4] = {pv.x, pv.y, pv.z, pv.w};
            float va[4] = {vv.x, vv.y, vv.z, vv.w};
#pragma unroll
            for (int i = 0; i < 4; i++)
#pragma unroll
                for (int j = 0; j < 4; j++)
                    o_[i][j] = fmaf(pa[i], va[j], o_[i][j]);
        }
        __syncthreads();
    }

    // epilogue: O / l -> g_att[b, row, h*64 + d]
#pragma unroll
    for (int i = 0; i < 4; i++) {
        float inv = 1.0f / l_[i];
        int row = i0 + ty * 4 + i;
        float4 ov = make_float4(o_[i][0] * inv, o_[i][1] * inv,
                                o_[i][2] * inv, o_[i][3] * inv);
        *(float4*)&g_att[((size_t)(b * N_ + row)) * C_ + h * HD + tx * 4] = ov;
    }
}

// ---------------------------------------------------------------------------
extern "C" void kernel_launch(void* const* d_in, const int* in_sizes, int n_in,
                              void* d_out, int out_size)
{
    const float* x          = (const float*)d_in[0];
    const float* qkv_w      = (const float*)d_in[1];
    const float* proj_w     = (const float*)d_in[2];
    const float* proj_b     = (const float*)d_in[3];
    const float* bias_table = (const float*)d_in[4];
    float* out = (float*)d_out;

    const int smem_attn = (4 * 64 * 68 + 128) * sizeof(float);  // ~70.5 KB
    cudaFuncSetAttribute(attn_kernel,
                         cudaFuncAttributeMaxDynamicSharedMemorySize, smem_attn);

    // 1) QKV projection: [32768,768] @ [2304,768]^T -> scatter to g_qkv
    gemm_nt<0><<<dim3(2304 / 64, 32768 / 128), 256>>>(x, qkv_w, nullptr, nullptr, C_);

    // 2) attention: 768 (b,h) pairs x 8 query tiles
    attn_kernel<<<dim3(N_ / 64, B_ * H_), 256, smem_attn>>>(bias_table);

    // 3) output projection: [32768,768] @ [768,768]^T + bias -> d_out
    gemm_nt<1><<<dim3(C_ / 64, 32768 / 128), 256>>>(nullptr, proj_w, proj_b, out, C_);
}

// round 5
// speedup vs baseline: 1.5551x; 1.5551x over previous
#include <cuda_runtime.h>
#include <math.h>

#define B_  64
#define N_  512
#define C_  768
#define H_  12
#define HD  64

// Scratch (allocation-free contract -> __device__ globals)
// g_qkv layout: [which][b][h][n][d]
__device__ float g_qkv[3ULL * B_ * H_ * N_ * HD];   // ~302 MB
// g_att layout: [b][n][h*64+d] == [M, C]
__device__ float g_att[(size_t)B_ * N_ * C_];       // ~100 MB

__device__ __forceinline__ unsigned f2tf32(float f) {
    unsigned r;
    asm("cvt.rna.tf32.f32 %0, %1;" : "=r"(r) : "f"(f));
    return r;
}

__device__ __forceinline__ void mma_tf32(float c[4],
                                         unsigned a0, unsigned a1, unsigned a2, unsigned a3,
                                         unsigned b0, unsigned b1) {
    asm volatile(
        "mma.sync.aligned.m16n8k8.row.col.f32.tf32.tf32.f32 "
        "{%0,%1,%2,%3}, {%4,%5,%6,%7}, {%8,%9}, {%0,%1,%2,%3};"
        : "+f"(c[0]), "+f"(c[1]), "+f"(c[2]), "+f"(c[3])
        : "r"(a0), "r"(a1), "r"(a2), "r"(a3), "r"(b0), "r"(b1));
}

// ---------------------------------------------------------------------------
// tf32 tensor-core GEMM: out = A[M,K] @ W[N,K]^T (both row-major, K contig).
// BM=BN=128, BK=16, 256 threads = 8 warps (4 M x 2 N), warp tile 32x64.
// m16n8k8 tf32 mma, fp32 accumulate.
// MODE 0: A = x, scatter into g_qkv. MODE 1: A = g_att, +bias -> out.
// ---------------------------------------------------------------------------
template<int MODE>
__global__ __launch_bounds__(256)
void gemm_tf32(const float* __restrict__ A,
               const float* __restrict__ W,
               const float* __restrict__ bias,
               float* __restrict__ out, int K)
{
    __shared__ unsigned As[128][20];   // [m][k], pad to 20 (conflict-free frag loads)
    __shared__ unsigned Ws[128][20];   // [n][k]

    const float* Ap = (MODE == 1) ? (const float*)g_att : A;

    int m0 = blockIdx.y * 128;
    int n0 = blockIdx.x * 128;
    int tid = threadIdx.x;
    int lane = tid & 31, warp = tid >> 5;
    int wm = warp >> 1;          // 0..3 (M)
    int wn = warp & 1;           // 0..1 (N)
    int g = lane >> 2, t = lane & 3;

    float acc[2][8][4];
#pragma unroll
    for (int mt = 0; mt < 2; mt++)
#pragma unroll
        for (int nt = 0; nt < 8; nt++)
#pragma unroll
            for (int r = 0; r < 4; r++) acc[mt][nt][r] = 0.f;

    // loader: each thread does 2 float4 from A and 2 from W per BK=16 slab
    int lrow = tid >> 1;             // 0..127
    int lk = (tid & 1) * 8;          // 0 or 8
    const float* aptr = Ap + (size_t)(m0 + lrow) * K + lk;
    const float* wptr = W  + (size_t)(n0 + lrow) * K + lk;

    float4 av0 = *(const float4*)(aptr + 0);
    float4 av1 = *(const float4*)(aptr + 4);
    float4 wv0 = *(const float4*)(wptr + 0);
    float4 wv1 = *(const float4*)(wptr + 4);

    for (int k0 = 0; k0 < K; k0 += 16) {
        // store current slab (converted to tf32)
        As[lrow][lk + 0] = f2tf32(av0.x); As[lrow][lk + 1] = f2tf32(av0.y);
        As[lrow][lk + 2] = f2tf32(av0.z); As[lrow][lk + 3] = f2tf32(av0.w);
        As[lrow][lk + 4] = f2tf32(av1.x); As[lrow][lk + 5] = f2tf32(av1.y);
        As[lrow][lk + 6] = f2tf32(av1.z); As[lrow][lk + 7] = f2tf32(av1.w);
        Ws[lrow][lk + 0] = f2tf32(wv0.x); Ws[lrow][lk + 1] = f2tf32(wv0.y);
        Ws[lrow][lk + 2] = f2tf32(wv0.z); Ws[lrow][lk + 3] = f2tf32(wv0.w);
        Ws[lrow][lk + 4] = f2tf32(wv1.x); Ws[lrow][lk + 5] = f2tf32(wv1.y);
        Ws[lrow][lk + 6] = f2tf32(wv1.z); Ws[lrow][lk + 7] = f2tf32(wv1.w);
        __syncthreads();

        // prefetch next slab while computing
        if (k0 + 16 < K) {
            av0 = *(const float4*)(aptr + k0 + 16);
            av1 = *(const float4*)(aptr + k0 + 20);
            wv0 = *(const float4*)(wptr + k0 + 16);
            wv1 = *(const float4*)(wptr + k0 + 20);
        }

#pragma unroll
        for (int ks = 0; ks < 2; ks++) {
            int kb = ks * 8;
            unsigned a[2][4];
#pragma unroll
            for (int mt = 0; mt < 2; mt++) {
                int r = wm * 32 + mt * 16 + g;
                a[mt][0] = As[r][kb + t];
                a[mt][1] = As[r + 8][kb + t];
                a[mt][2] = As[r][kb + t + 4];
                a[mt][3] = As[r + 8][kb + t + 4];
            }
#pragma unroll
            for (int nt = 0; nt < 8; nt++) {
                int c = wn * 64 + nt * 8 + g;
                unsigned b0 = Ws[c][kb + t];
                unsigned b1 = Ws[c][kb + t + 4];
#pragma unroll
                for (int mt = 0; mt < 2; mt++)
                    mma_tf32(acc[mt][nt], a[mt][0], a[mt][1], a[mt][2], a[mt][3], b0, b1);
            }
        }
        __syncthreads();
    }

    // epilogue: c-frag thread mapping: rows g, g+8; cols 2t, 2t+1
#pragma unroll
    for (int mt = 0; mt < 2; mt++) {
#pragma unroll
        for (int nt = 0; nt < 8; nt++) {
            int n = n0 + wn * 64 + nt * 8 + 2 * t;
#pragma unroll
            for (int half = 0; half < 2; half++) {
                int m = m0 + wm * 32 + mt * 16 + g + half * 8;
                float2 val = make_float2(acc[mt][nt][half * 2],
                                         acc[mt][nt][half * 2 + 1]);
                if (MODE == 0) {
                    int which = n / C_;
                    int rem = n - which * C_;
                    int h = rem >> 6;
                    int d = rem & 63;
                    int b = m >> 9;
                    int nn = m & 511;
                    float* dst = g_qkv + (size_t)which * (B_ * H_ * N_ * HD)
                               + (((size_t)(b * H_ + h) * N_ + nn) * HD) + d;
                    *(float2*)dst = val;
                } else {
                    val.x += bias[n];
                    val.y += bias[n + 1];
                    *(float2*)(out + (size_t)m * C_ + n) = val;
                }
            }
        }
    }
}

// ---------------------------------------------------------------------------
// Flash-style attention: one CTA per (b,h, 64-query tile). 256 threads.
// ---------------------------------------------------------------------------
__global__ __launch_bounds__(256)
void attn_kernel(const float* __restrict__ bias_table)
{
    const int ST = 68;
    extern __shared__ float sm[];
    float* Qs  = sm;               // [64][68]  Qs[d][row]
    float* Ks  = Qs + 64 * ST;     // [64][68]  Ks[d][key]
    float* Vs  = Ks + 64 * ST;     // [64][68]  Vs[k][d]
    float* Ps  = Vs + 64 * ST;     // [64][68]  Ps[k][row]
    float* bsh = Ps + 64 * ST;     // [127]

    int bh = blockIdx.y;           // 0..767
    int b = bh / H_;
    int h = bh - b * H_;
    int i0 = blockIdx.x * 64;

    const float* qb = g_qkv + (size_t)bh * N_ * HD;
    const float* kb = qb + (size_t)B_ * H_ * N_ * HD;
    const float* vb = kb + (size_t)B_ * H_ * N_ * HD;

    int tid = threadIdx.x;
    int tx = tid & 15;
    int ty = tid >> 4;

    // load Q tile transposed, float4 global loads (HD contiguous)
    for (int idx = tid; idx < 1024; idx += 256) {
        int r = idx >> 4;            // 0..63
        int dq = (idx & 15) * 4;     // 0,4,...,60
        float4 v = *(const float4*)(qb + (size_t)(i0 + r) * HD + dq);
        Qs[(dq + 0) * ST + r] = v.x;
        Qs[(dq + 1) * ST + r] = v.y;
        Qs[(dq + 2) * ST + r] = v.z;
        Qs[(dq + 3) * ST + r] = v.w;
    }

    float m_[4], l_[4], o_[4][4];
#pragma unroll
    for (int i = 0; i < 4; i++) {
        m_[i] = -1e30f; l_[i] = 0.f;
#pragma unroll
        for (int j = 0; j < 4; j++) o_[i][j] = 0.f;
    }

    const float scale = 0.125f;   // hd^-0.5 = 1/8

    for (int kt = 0; kt < 8; kt++) {
        for (int idx = tid; idx < 1024; idx += 256) {
            int r = idx >> 4;
            int dq = (idx & 15) * 4;
            float4 kv4 = *(const float4*)(kb + (size_t)(kt * 64 + r) * HD + dq);
            float4 vv4 = *(const float4*)(vb + (size_t)(kt * 64 + r) * HD + dq);
            Ks[(dq + 0) * ST + r] = kv4.x;
            Ks[(dq + 1) * ST + r] = kv4.y;
            Ks[(dq + 2) * ST + r] = kv4.z;
            Ks[(dq + 3) * ST + r] = kv4.w;
            *(float4*)&Vs[r * ST + dq] = vv4;
        }
        // bias slab: rel = i - j + 511, local t = (i-i0)-(j-j0)+63 in [0,126]
        if (tid < 127) {
            int rel = i0 - kt * 64 + 448 + tid;
            bsh[tid] = bias_table[rel * H_ + h];
        }
        __syncthreads();

        // S = Q K^T
        float s[4][4];
#pragma unroll
        for (int i = 0; i < 4; i++)
#pragma unroll
            for (int j = 0; j < 4; j++) s[i][j] = 0.f;

#pragma unroll 8
        for (int d = 0; d < 64; d++) {
            float4 qv = *(const float4*)&Qs[d * ST + ty * 4];
            float4 kv = *(const float4*)&Ks[d * ST + tx * 4];
            float qa[4] = {qv.x, qv.y, qv.z, qv.w};
            float ka[4] = {kv.x, kv.y, kv.z, kv.w};
#pragma unroll
            for (int i = 0; i < 4; i++)
#pragma unroll
                for (int j = 0; j < 4; j++)
                    s[i][j] = fmaf(qa[i], ka[j], s[i][j]);
        }

        // scale + bias, tile row-max
        float mt[4];
#pragma unroll
        for (int i = 0; i < 4; i++) {
            mt[i] = -1e30f;
#pragma unroll
            for (int j = 0; j < 4; j++) {
                s[i][j] = s[i][j] * scale + bsh[(ty * 4 + i) - (tx * 4 + j) + 63];
                mt[i] = fmaxf(mt[i], s[i][j]);
            }
        }
#pragma unroll
        for (int off = 8; off > 0; off >>= 1)
#pragma unroll
            for (int i = 0; i < 4; i++)
                mt[i] = fmaxf(mt[i], __shfl_xor_sync(0xffffffffu, mt[i], off, 16));

        // online softmax update
        float alpha[4], rs[4];
#pragma unroll
        for (int i = 0; i < 4; i++) {
            float mn = fmaxf(m_[i], mt[i]);
            alpha[i] = __expf(m_[i] - mn);
            m_[i] = mn;
            float r = 0.f;
#pragma unroll
            for (int j = 0; j < 4; j++) {
                s[i][j] = __expf(s[i][j] - mn);
                r += s[i][j];
            }
            rs[i] = r;
        }
#pragma unroll
        for (int off = 8; off > 0; off >>= 1)
#pragma unroll
            for (int i = 0; i < 4; i++)
                rs[i] += __shfl_xor_sync(0xffffffffu, rs[i], off, 16);
#pragma unroll
        for (int i = 0; i < 4; i++) {
            l_[i] = l_[i] * alpha[i] + rs[i];
#pragma unroll
            for (int j = 0; j < 4; j++) o_[i][j] *= alpha[i];
        }

        // write P transposed: Ps[key][row]
#pragma unroll
        for (int j = 0; j < 4; j++)
#pragma unroll
            for (int i = 0; i < 4; i++)
                Ps[(tx * 4 + j) * ST + ty * 4 + i] = s[i][j];
        __syncthreads();

        // O += P @ V
#pragma unroll 8
        for (int kk = 0; kk < 64; kk++) {
            float4 pv = *(const float4*)&Ps[kk * ST + ty * 4];
            float4 vv = *(const float4*)&Vs[kk * ST + tx * 4];
            float pa[4] = {pv.x, pv.y, pv.z, pv.w};
            float va[4] = {vv.x, vv.y, vv.z, vv.w};
#pragma unroll
            for (int i = 0; i < 4; i++)
#pragma unroll
                for (int j = 0; j < 4; j++)
                    o_[i][j] = fmaf(pa[i], va[j], o_[i][j]);
        }
        __syncthreads();
    }

    // epilogue: O / l -> g_att[b, row, h*64 + d]
#pragma unroll
    for (int i = 0; i < 4; i++) {
        float inv = 1.0f / l_[i];
        int row = i0 + ty * 4 + i;
        float4 ov = make_float4(o_[i][0] * inv, o_[i][1] * inv,
                                o_[i][2] * inv, o_[i][3] * inv);
        *(float4*)&g_att[((size_t)(b * N_ + row)) * C_ + h * HD + tx * 4] = ov;
    }
}

// ---------------------------------------------------------------------------
extern "C" void kernel_launch(void* const* d_in, const int* in_sizes, int n_in,
                              void* d_out, int out_size)
{
    const float* x          = (const float*)d_in[0];
    const float* qkv_w      = (const float*)d_in[1];
    const float* proj_w     = (const float*)d_in[2];
    const float* proj_b     = (const float*)d_in[3];
    const float* bias_table = (const float*)d_in[4];
    float* out = (float*)d_out;

    const int smem_attn = (4 * 64 * 68 + 128) * sizeof(float);  // ~70.5 KB
    cudaFuncSetAttribute(attn_kernel,
                         cudaFuncAttributeMaxDynamicSharedMemorySize, smem_attn);

    // 1) QKV projection: [32768,768] @ [2304,768]^T -> scatter to g_qkv
    gemm_tf32<0><<<dim3(2304 / 128, 32768 / 128), 256>>>(x, qkv_w, nullptr, nullptr, C_);

    // 2) attention: 768 (b,h) pairs x 8 query tiles
    attn_kernel<<<dim3(N_ / 64, B_ * H_), 256, smem_attn>>>(bias_table);

    // 3) output projection: [32768,768] @ [768,768]^T + bias -> d_out
    gemm_tf32<1><<<dim3(C_ / 128, 32768 / 128), 256>>>(nullptr, proj_w, proj_b, out, C_);
}

// round 7
// speedup vs baseline: 3.2740x; 2.1053x over previous
#include <cuda_runtime.h>
#include <math.h>

#define B_  64
#define N_  512
#define C_  768
#define H_  12
#define HD  64

#define QS  ((size_t)B_ * H_ * N_ * HD)   // per-matrix stride in g_qkv

// Scratch (allocation-free contract -> __device__ globals)
// Q region: [b][h][n][d]; K region: [b][h][n][d]; V region: [b][h][d][n] (pre-transposed!)
__device__ float g_qkv[3 * QS];                    // ~302 MB
__device__ float g_att[(size_t)B_ * N_ * C_];      // ~100 MB

__device__ __forceinline__ unsigned f2tf32(float f) {
    unsigned r;
    asm("cvt.rna.tf32.f32 %0, %1;" : "=r"(r) : "f"(f));
    return r;
}
__device__ __forceinline__ float f2tf32f(float f) {
    return __uint_as_float(f2tf32(f));
}

__device__ __forceinline__ void mma_tf32(float c[4],
                                         unsigned a0, unsigned a1, unsigned a2, unsigned a3,
                                         unsigned b0, unsigned b1) {
    asm volatile(
        "mma.sync.aligned.m16n8k8.row.col.f32.tf32.tf32.f32 "
        "{%0,%1,%2,%3}, {%4,%5,%6,%7}, {%8,%9}, {%0,%1,%2,%3};"
        : "+f"(c[0]), "+f"(c[1]), "+f"(c[2]), "+f"(c[3])
        : "r"(a0), "r"(a1), "r"(a2), "r"(a3), "r"(b0), "r"(b1));
}

__device__ __forceinline__ void cp_async16(unsigned dst, const void* src) {
    asm volatile("cp.async.ca.shared.global [%0], [%1], 16;" :: "r"(dst), "l"(src));
}
__device__ __forceinline__ void cp_commit() {
    asm volatile("cp.async.commit_group;");
}
template<int N>
__device__ __forceinline__ void cp_wait() {
    asm volatile("cp.async.wait_group %0;" :: "n"(N));
}

// ---------------------------------------------------------------------------
// tf32 GEMM v2: out = A[M,K] @ W[N,K]^T. CTA 128x128, 4 warps (2x2), warp 64x64.
// BK=32, cp.async double-buffered, stride-36 smem (conflict-free STS.128 + LDS).
// MODE 0: A = x, scatter to g_qkv (V transposed). MODE 1: A = g_att, +bias -> out.
// ---------------------------------------------------------------------------
#define GST 36
#define GBUF (128 * GST)

template<int MODE>
__global__ __launch_bounds__(128)
void gemm_tf32(const float* __restrict__ A,
               const float* __restrict__ W,
               const float* __restrict__ bias,
               float* __restrict__ out, int K)
{
    extern __shared__ float smg[];
    float* As = smg;                 // [2][128][36]
    float* Ws = smg + 2 * GBUF;      // [2][128][36]

    const float* Ap = (MODE == 1) ? (const float*)g_att : A;

    int m0 = blockIdx.y * 128;
    int n0 = blockIdx.x * 128;
    int tid = threadIdx.x;
    int lane = tid & 31, warp = tid >> 5;
    int wm = warp >> 1, wn = warp & 1;
    int g = lane >> 2, t = lane & 3;

    unsigned sbase = (unsigned)__cvta_generic_to_shared(smg);

    float acc[4][8][4];
#pragma unroll
    for (int mt = 0; mt < 4; mt++)
#pragma unroll
        for (int nt = 0; nt < 8; nt++)
#pragma unroll
            for (int r = 0; r < 4; r++) acc[mt][nt][r] = 0.f;

    int lr = tid >> 3;            // 0..15
    int lkq = (tid & 7) * 4;      // 0..28

    const int NS = K / 32;

    // stage slab s into buffer buf
    auto stage = [&](int s, int buf) {
        int k0 = s * 32;
#pragma unroll
        for (int p = 0; p < 8; p++) {
            int r = p * 16 + lr;
            unsigned dA = sbase + (unsigned)((buf * GBUF + r * GST + lkq) * 4);
            unsigned dW = sbase + (unsigned)((2 * GBUF + buf * GBUF + r * GST + lkq) * 4);
            cp_async16(dA, Ap + (size_t)(m0 + r) * K + k0 + lkq);
            cp_async16(dW, W  + (size_t)(n0 + r) * K + k0 + lkq);
        }
    };

    stage(0, 0);
    cp_commit();

    for (int s = 0; s < NS; s++) {
        if (s + 1 < NS) {
            stage(s + 1, (s + 1) & 1);
            cp_commit();
            cp_wait<1>();
        } else {
            cp_wait<0>();
        }
        __syncthreads();

        const float* Ab = As + (s & 1) * GBUF;
        const float* Wb = Ws + (s & 1) * GBUF;

#pragma unroll
        for (int kb = 0; kb < 32; kb += 8) {
            unsigned a[4][4];
#pragma unroll
            for (int mt = 0; mt < 4; mt++) {
                int r = wm * 64 + mt * 16 + g;
                a[mt][0] = f2tf32(Ab[r * GST + kb + t]);
                a[mt][1] = f2tf32(Ab[(r + 8) * GST + kb + t]);
                a[mt][2] = f2tf32(Ab[r * GST + kb + t + 4]);
                a[mt][3] = f2tf32(Ab[(r + 8) * GST + kb + t + 4]);
            }
#pragma unroll
            for (int nt = 0; nt < 8; nt++) {
                int c = wn * 64 + nt * 8 + g;
                unsigned b0 = f2tf32(Wb[c * GST + kb + t]);
                unsigned b1 = f2tf32(Wb[c * GST + kb + t + 4]);
#pragma unroll
                for (int mt = 0; mt < 4; mt++)
                    mma_tf32(acc[mt][nt], a[mt][0], a[mt][1], a[mt][2], a[mt][3], b0, b1);
            }
        }
        __syncthreads();
    }

    // epilogue
#pragma unroll
    for (int mt = 0; mt < 4; mt++) {
#pragma unroll
        for (int nt = 0; nt < 8; nt++) {
            int n = n0 + wn * 64 + nt * 8 + 2 * t;
#pragma unroll
            for (int half = 0; half < 2; half++) {
                int m = m0 + wm * 64 + mt * 16 + g + half * 8;
                float2 val = make_float2(acc[mt][nt][half * 2],
                                         acc[mt][nt][half * 2 + 1]);
                if (MODE == 0) {
                    int which = n / C_;
                    int rem = n - which * C_;
                    int h = rem >> 6;
                    int d = rem & 63;
                    int b = m >> 9;
                    int nn = m & 511;
                    if (which < 2) {
                        float* dst = g_qkv + (size_t)which * QS
                                   + (((size_t)(b * H_ + h) * N_ + nn) * HD) + d;
                        *(float2*)dst = val;
                    } else {
                        // V transposed: [b][h][d][n]
                        float* dst = g_qkv + 2 * QS
                                   + ((size_t)(b * H_ + h) * HD + d) * N_ + nn;
                        dst[0] = val.x;
                        dst[N_] = val.y;
                    }
                } else {
                    val.x += bias[n];
                    val.y += bias[n + 1];
                    *(float2*)(out + (size_t)m * C_ + n) = val;
                }
            }
        }
    }
}

// ---------------------------------------------------------------------------
// tf32 tensor-core flash attention. CTA = (b,h, 64-q-tile), 128 threads, 4 warps.
// Each warp owns 16 q-rows. Q pre-scaled, kept as a-frags in registers.
// Ks[key][d], Vs[d][key] (V pre-transposed in gmem), Ps[q][key]; stride 68.
// ---------------------------------------------------------------------------
__global__ __launch_bounds__(128)
void attn_kernel(const float* __restrict__ bias_table)
{
    const int ST = 68;
    extern __shared__ float sm[];
    float* Ks  = sm;               // [64][68]  Ks[key][d]   (tf32 values)
    float* Vs  = Ks + 64 * ST;     // [64][68]  Vs[d][key]   (tf32 values)
    float* Ps  = Vs + 64 * ST;     // [64][68]  Ps[q][key]; also Q staging
    float* bsh = Ps + 64 * ST;     // [128]

    int bh = blockIdx.y;
    int b = bh / H_;
    int h = bh - b * H_;
    int i0 = blockIdx.x * 64;

    const float* qb  = g_qkv + (size_t)bh * N_ * HD;
    const float* kgb = qb + QS;
    const float* vbt = g_qkv + 2 * QS + (size_t)bh * HD * N_;  // [d][n]

    int tid = threadIdx.x;
    int lane = tid & 31, warp = tid >> 5;
    int g = lane >> 2, t = lane & 3;
    int q0 = warp * 16;

    // stage Q (raw fp32) into Ps
    for (int i = tid; i < 1024; i += 128) {
        int r = i >> 4, dq = (i & 15) * 4;
        *(float4*)&Ps[r * ST + dq] = *(const float4*)(qb + (size_t)(i0 + r) * HD + dq);
    }
    __syncthreads();

    // Q a-frags (pre-scaled by 1/8, tf32)
    unsigned qa[8][4];
#pragma unroll
    for (int kb = 0; kb < 8; kb++) {
        qa[kb][0] = f2tf32(0.125f * Ps[(q0 + g) * ST + kb * 8 + t]);
        qa[kb][1] = f2tf32(0.125f * Ps[(q0 + g + 8) * ST + kb * 8 + t]);
        qa[kb][2] = f2tf32(0.125f * Ps[(q0 + g) * ST + kb * 8 + t + 4]);
        qa[kb][3] = f2tf32(0.125f * Ps[(q0 + g + 8) * ST + kb * 8 + t + 4]);
    }
    __syncthreads();

    float m_[2] = {-1e30f, -1e30f};
    float l_[2] = {0.f, 0.f};
    float o_[8][4];
#pragma unroll
    for (int nt = 0; nt < 8; nt++)
#pragma unroll
        for (int r = 0; r < 4; r++) o_[nt][r] = 0.f;

    for (int kt = 0; kt < 8; kt++) {
        // K tile -> Ks[key][d] (cvt to tf32 at staging)
        for (int i = tid; i < 1024; i += 128) {
            int r = i >> 4, dq = (i & 15) * 4;
            float4 v = *(const float4*)(kgb + (size_t)(kt * 64 + r) * HD + dq);
            float4 o4 = make_float4(f2tf32f(v.x), f2tf32f(v.y), f2tf32f(v.z), f2tf32f(v.w));
            *(float4*)&Ks[r * ST + dq] = o4;
        }
        // V^T tile -> Vs[d][key]
        for (int i = tid; i < 1024; i += 128) {
            int d = i >> 4, kq = (i & 15) * 4;
            float4 v = *(const float4*)(vbt + (size_t)d * N_ + kt * 64 + kq);
            float4 o4 = make_float4(f2tf32f(v.x), f2tf32f(v.y), f2tf32f(v.z), f2tf32f(v.w));
            *(float4*)&Vs[d * ST + kq] = o4;
        }
        if (tid < 127)
            bsh[tid] = bias_table[(i0 - kt * 64 + 448 + tid) * H_ + h];
        __syncthreads();

        // S = (Q/8) K^T
        float s[8][4];
#pragma unroll
        for (int nt = 0; nt < 8; nt++)
#pragma unroll
            for (int r = 0; r < 4; r++) s[nt][r] = 0.f;

#pragma unroll
        for (int kb = 0; kb < 8; kb++) {
#pragma unroll
            for (int nt = 0; nt < 8; nt++) {
                unsigned b0 = __float_as_uint(Ks[(nt * 8 + g) * ST + kb * 8 + t]);
                unsigned b1 = __float_as_uint(Ks[(nt * 8 + g) * ST + kb * 8 + t + 4]);
                mma_tf32(s[nt], qa[kb][0], qa[kb][1], qa[kb][2], qa[kb][3], b0, b1);
            }
        }

        // bias + row max (rows r0 = q0+g, r1 = q0+g+8 local)
        float mt2[2] = {-1e30f, -1e30f};
#pragma unroll
        for (int nt = 0; nt < 8; nt++) {
            int jl = nt * 8 + 2 * t;
            s[nt][0] += bsh[(q0 + g) - jl + 63];
            s[nt][1] += bsh[(q0 + g) - jl + 62];
            s[nt][2] += bsh[(q0 + g + 8) - jl + 63];
            s[nt][3] += bsh[(q0 + g + 8) - jl + 62];
            mt2[0] = fmaxf(mt2[0], fmaxf(s[nt][0], s[nt][1]));
            mt2[1] = fmaxf(mt2[1], fmaxf(s[nt][2], s[nt][3]));
        }
        mt2[0] = fmaxf(mt2[0], __shfl_xor_sync(0xffffffffu, mt2[0], 1));
        mt2[0] = fmaxf(mt2[0], __shfl_xor_sync(0xffffffffu, mt2[0], 2));
        mt2[1] = fmaxf(mt2[1], __shfl_xor_sync(0xffffffffu, mt2[1], 1));
        mt2[1] = fmaxf(mt2[1], __shfl_xor_sync(0xffffffffu, mt2[1], 2));

        float mn0 = fmaxf(m_[0], mt2[0]);
        float mn1 = fmaxf(m_[1], mt2[1]);
        float al0 = __expf(m_[0] - mn0);
        float al1 = __expf(m_[1] - mn1);
        m_[0] = mn0; m_[1] = mn1;

        float rs0 = 0.f, rs1 = 0.f;
#pragma unroll
        for (int nt = 0; nt < 8; nt++) {
            s[nt][0] = __expf(s[nt][0] - mn0);
            s[nt][1] = __expf(s[nt][1] - mn0);
            s[nt][2] = __expf(s[nt][2] - mn1);
            s[nt][3] = __expf(s[nt][3] - mn1);
            rs0 += s[nt][0] + s[nt][1];
            rs1 += s[nt][2] + s[nt][3];
        }
        rs0 += __shfl_xor_sync(0xffffffffu, rs0, 1);
        rs0 += __shfl_xor_sync(0xffffffffu, rs0, 2);
        rs1 += __shfl_xor_sync(0xffffffffu, rs1, 1);
        rs1 += __shfl_xor_sync(0xffffffffu, rs1, 2);
        l_[0] = l_[0] * al0 + rs0;
        l_[1] = l_[1] * al1 + rs1;
#pragma unroll
        for (int nt = 0; nt < 8; nt++) {
            o_[nt][0] *= al0; o_[nt][1] *= al0;
            o_[nt][2] *= al1; o_[nt][3] *= al1;
        }

        // store P (tf32) to Ps[q][key] (warp-private rows)
#pragma unroll
        for (int nt = 0; nt < 8; nt++) {
            int col = nt * 8 + 2 * t;
            *(float2*)&Ps[(q0 + g) * ST + col] =
                make_float2(f2tf32f(s[nt][0]), f2tf32f(s[nt][1]));
            *(float2*)&Ps[(q0 + g + 8) * ST + col] =
                make_float2(f2tf32f(s[nt][2]), f2tf32f(s[nt][3]));
        }
        __syncwarp();

        // O += P V
#pragma unroll
        for (int kb = 0; kb < 8; kb++) {
            unsigned pa0 = __float_as_uint(Ps[(q0 + g) * ST + kb * 8 + t]);
            unsigned pa1 = __float_as_uint(Ps[(q0 + g + 8) * ST + kb * 8 + t]);
            unsigned pa2 = __float_as_uint(Ps[(q0 + g) * ST + kb * 8 + t + 4]);
            unsigned pa3 = __float_as_uint(Ps[(q0 + g + 8) * ST + kb * 8 + t + 4]);
#pragma unroll
            for (int nt = 0; nt < 8; nt++) {
                unsigned b0 = __float_as_uint(Vs[(nt * 8 + g) * ST + kb * 8 + t]);
                unsigned b1 = __float_as_uint(Vs[(nt * 8 + g) * ST + kb * 8 + t + 4]);
                mma_tf32(o_[nt], pa0, pa1, pa2, pa3, b0, b1);
            }
        }
        __syncthreads();
    }

    // epilogue: O / l -> g_att[b][row][h*64 + d]
    float inv0 = 1.0f / l_[0];
    float inv1 = 1.0f / l_[1];
    int r0 = i0 + q0 + g;
    int r1 = r0 + 8;
#pragma unroll
    for (int nt = 0; nt < 8; nt++) {
        int col = h * 64 + nt * 8 + 2 * t;
        *(float2*)&g_att[((size_t)(b * N_ + r0)) * C_ + col] =
            make_float2(o_[nt][0] * inv0, o_[nt][1] * inv0);
        *(float2*)&g_att[((size_t)(b * N_ + r1)) * C_ + col] =
            make_float2(o_[nt][2] * inv1, o_[nt][3] * inv1);
    }
}

// ---------------------------------------------------------------------------
extern "C" void kernel_launch(void* const* d_in, const int* in_sizes, int n_in,
                              void* d_out, int out_size)
{
    const float* x          = (const float*)d_in[0];
    const float* qkv_w      = (const float*)d_in[1];
    const float* proj_w     = (const float*)d_in[2];
    const float* proj_b     = (const float*)d_in[3];
    const float* bias_table = (const float*)d_in[4];
    float* out = (float*)d_out;

    const int smem_gemm = 4 * GBUF * sizeof(float);              // 73728 B
    const int smem_attn = (3 * 64 * 68 + 128) * sizeof(float);   // 52736 B

    cudaFuncSetAttribute(gemm_tf32<0>,
                         cudaFuncAttributeMaxDynamicSharedMemorySize, smem_gemm);
    cudaFuncSetAttribute(gemm_tf32<1>,
                         cudaFuncAttributeMaxDynamicSharedMemorySize, smem_gemm);
    cudaFuncSetAttribute(attn_kernel,
                         cudaFuncAttributeMaxDynamicSharedMemorySize, smem_attn);

    // 1) QKV projection: [32768,768] @ [2304,768]^T -> g_qkv (V transposed)
    gemm_tf32<0><<<dim3(2304 / 128, 32768 / 128), 128, smem_gemm>>>(
        x, qkv_w, nullptr, nullptr, C_);

    // 2) attention: 768 (b,h) pairs x 8 query tiles
    attn_kernel<<<dim3(N_ / 64, B_ * H_), 128, smem_attn>>>(bias_table);

    // 3) output projection: [32768,768] @ [768,768]^T + bias -> d_out
    gemm_tf32<1><<<dim3(C_ / 128, 32768 / 128), 128, smem_gemm>>>(
        nullptr, proj_w, proj_b, out, C_);
}